// round 17
// baseline (speedup 1.0000x reference)
#include <cuda_runtime.h>
#include <cuda_fp16.h>
#include <cstdint>

#define N_E   200000
#define N_T   1000000
#define N_R   200
#define N_W2V 300
#define BB    64        // batch
#define STRIP 8         // triples per thread-strip

#define TB_TILES ((N_E + 31) / 32)              // 6250 transpose blocks
#define CR_BLKS  ((3 * N_R + 7) / 8)            // 75 compute_r blocks (8 warps)

// fp16 gather-side state: (N_E, 64) halves, 128B rows. 25.6 MB.
__device__ __align__(256) __half g_x16[(size_t)N_E * BB];
// fp32 accumulator state: (N_E, 64) floats, 256B rows. 51.2 MB. Pre-zeroed.
__device__ __align__(256) float  g_y32[(size_t)N_E * BB];
// Precomputed r for all 3 hops, relation-major fp16: rt[h][j][b]
__device__ __align__(256) __half g_rt16[3][N_R * BB];

// CSR-sort scratch, rebuilt every call.
#define SCAN_BLOCK 2048
#define SCAN_NBLK  ((N_E + SCAN_BLOCK - 1) / SCAN_BLOCK)   // 98
__device__ unsigned g_hist[N_E];
__device__ unsigned g_cursor[N_E];
__device__ unsigned g_bsum[SCAN_NBLK];
// Sorted-by-obj triple stream: .x = (subj<<8)|rel (26 bits), .y = obj. 8 MB.
__device__ __align__(16) uint2 g_sp[N_T];

struct __align__(8) h4 { __half2 a, b; };   // 4 halves = 8 bytes

// ---------------------------------------------------------------------------
// Fused: blocks [0, TB_TILES) transpose x -> g_x16 fp16 + zero g_y32 + zero
// g_hist; blocks [TB_TILES, +CR_BLKS) compute_r (warp per (h, j)). The 75
// compute blocks fill wave-1 scheduler slack under the bandwidth-bound
// transpose (unlike R14's 977 contending histogram blocks).
// ---------------------------------------------------------------------------
__global__ void __launch_bounds__(256)
transpose_in(const float* __restrict__ x,  const float* __restrict__ q,
             const float* __restrict__ W1, const float* __restrict__ b1,
             const float* __restrict__ W2, const float* __restrict__ b2,
             const float* __restrict__ W3, const float* __restrict__ b3) {
    __shared__ float tile[32][BB + 1];
    const int tid  = threadIdx.x;
    const int lane = tid & 31;
    const int warp = tid >> 5;

    if (blockIdx.x >= TB_TILES) {
        // ---- compute_r: one warp per (h, j), 600 units ----------------------
        const int w = (blockIdx.x - TB_TILES) * 8 + warp;
        if (w < 3 * N_R) {
            const int h = w / N_R;
            const int j = w - h * N_R;
            const float* __restrict__ W  = (h == 0) ? W1 : (h == 1) ? W2 : W3;
            const float* __restrict__ bv = (h == 0) ? b1 : (h == 1) ? b2 : b3;
            float a0 = bv[j], a1 = a0;
            const float* __restrict__ q0 = q + (size_t)lane * N_W2V;
            const float* __restrict__ q1 = q + (size_t)(lane + 32) * N_W2V;
#pragma unroll 4
            for (int k = 0; k < N_W2V; ++k) {
                const float wk = __ldg(W + (size_t)k * N_R + j);  // warp-broadcast
                a0 = fmaf(q0[k], wk, a0);
                a1 = fmaf(q1[k], wk, a1);
            }
            g_rt16[h][j * BB + lane]      = __float2half_rn(a0);
            g_rt16[h][j * BB + lane + 32] = __float2half_rn(a1);
        }
        return;
    }

    // ---- transpose + zero ---------------------------------------------------
    const int e0 = blockIdx.x * 32;
    for (int b = warp; b < BB; b += 8) {
        const int e = e0 + lane;
        tile[lane][b] = (e < N_E) ? x[(size_t)b * N_E + e] : 0.f;
    }
    {   // zero my y32 slice (6250 blocks * 512 float4 = N_E*BB) + 32 hist bins
        float4* __restrict__ y4 = reinterpret_cast<float4*>(g_y32);
        const size_t base = (size_t)blockIdx.x * 512 + tid;
        const float4 z = make_float4(0.f, 0.f, 0.f, 0.f);
        y4[base]       = z;
        y4[base + 256] = z;
        if (tid < 32 && e0 + tid < N_E) g_hist[e0 + tid] = 0u;
    }
    __syncthreads();

    const int l16 = tid & 15;
    for (int er = tid >> 4; er < 32; er += 16) {
        const int e = e0 + er;
        if (e < N_E) {
            h4 v;
            v.a = __floats2half2_rn(tile[er][l16 * 4 + 0], tile[er][l16 * 4 + 1]);
            v.b = __floats2half2_rn(tile[er][l16 * 4 + 2], tile[er][l16 * 4 + 3]);
            reinterpret_cast<h4*>(g_x16 + (size_t)e * BB)[l16] = v;
        }
    }
}

// ---------------------------------------------------------------------------
// Histogram of obj: 8 triples per thread (2x int4, MLP 8).
// ---------------------------------------------------------------------------
__global__ void csr_count(const int* __restrict__ obj) {
    const int i  = blockIdx.x * blockDim.x + threadIdx.x;
    const int t0 = i * 8;
    if (t0 >= N_T) return;
    const int4 a = __ldg(reinterpret_cast<const int4*>(obj + t0));
    const int4 b = __ldg(reinterpret_cast<const int4*>(obj + t0 + 4));
    atomicAdd(&g_hist[a.x], 1u);
    atomicAdd(&g_hist[a.y], 1u);
    atomicAdd(&g_hist[a.z], 1u);
    atomicAdd(&g_hist[a.w], 1u);
    atomicAdd(&g_hist[b.x], 1u);
    atomicAdd(&g_hist[b.y], 1u);
    atomicAdd(&g_hist[b.z], 1u);
    atomicAdd(&g_hist[b.w], 1u);
}

// ---------------------------------------------------------------------------
// Scan stage 1, shuffle form: 512 threads x 4 elements, one barrier.
// Partial exclusive scan to g_cursor; block total to g_bsum.
// ---------------------------------------------------------------------------
__global__ void __launch_bounds__(512)
csr_scan1() {
    __shared__ unsigned wsum[16];
    const int tid  = threadIdx.x;
    const int lane = tid & 31;
    const int warp = tid >> 5;
    const int base = blockIdx.x * SCAN_BLOCK + tid * 4;

    unsigned v0 = (base     < N_E) ? g_hist[base]     : 0u;
    unsigned v1 = (base + 1 < N_E) ? g_hist[base + 1] : 0u;
    unsigned v2 = (base + 2 < N_E) ? g_hist[base + 2] : 0u;
    unsigned v3 = (base + 3 < N_E) ? g_hist[base + 3] : 0u;
    const unsigned mysum = v0 + v1 + v2 + v3;

    unsigned incl = mysum;
#pragma unroll
    for (int off = 1; off < 32; off <<= 1) {
        const unsigned u = __shfl_up_sync(0xFFFFFFFFu, incl, off);
        if (lane >= off) incl += u;
    }
    if (lane == 31) wsum[warp] = incl;
    __syncthreads();
    if (warp == 0 && lane < 16) {
        unsigned s = wsum[lane];
#pragma unroll
        for (int off = 1; off < 16; off <<= 1) {
            const unsigned u = __shfl_up_sync(0xFFFFu, s, off);
            if (lane >= off) s += u;
        }
        wsum[lane] = s;                          // inclusive warp-sum scan
        if (lane == 15) g_bsum[blockIdx.x] = s;  // block total
    }
    __syncthreads();

    const unsigned woff = (warp > 0) ? wsum[warp - 1] : 0u;
    unsigned excl = woff + incl - mysum;
    if (base     < N_E) g_cursor[base]     = excl;
    if (base + 1 < N_E) g_cursor[base + 1] = excl + v0;
    if (base + 2 < N_E) g_cursor[base + 2] = excl + v0 + v1;
    if (base + 3 < N_E) g_cursor[base + 3] = excl + v0 + v1 + v2;
}

// ---------------------------------------------------------------------------
// Scan stages 2+3 fused: each 256-entity block reduces the bsum prefix it
// needs (<= 98 values) in smem, then adds it to its cursors.
// ---------------------------------------------------------------------------
__global__ void __launch_bounds__(256)
csr_scan23() {
    __shared__ unsigned s[128];
    const int tid = threadIdx.x;
    const int k   = blockIdx.x >> 3;   // which 2048-entity region (256*8)
    if (tid < 128) s[tid] = (tid < k && tid < SCAN_NBLK) ? g_bsum[tid] : 0u;
    __syncthreads();
    for (int off = 64; off > 0; off >>= 1) {
        if (tid < off) s[tid] += s[tid + off];
        __syncthreads();
    }
    const unsigned pref = s[0];
    const int i = blockIdx.x * 256 + tid;
    if (i < N_E) g_cursor[i] += pref;
}

// ---------------------------------------------------------------------------
// Slot scatter: 8 triples per thread (2x int4 per index array, MLP 8).
// ---------------------------------------------------------------------------
__global__ void csr_scatter(const int* __restrict__ subj,
                            const int* __restrict__ rel,
                            const int* __restrict__ obj) {
    const int i  = blockIdx.x * blockDim.x + threadIdx.x;
    const int t0 = i * 8;
    if (t0 >= N_T) return;
    const int4 sa = __ldg(reinterpret_cast<const int4*>(subj + t0));
    const int4 sb = __ldg(reinterpret_cast<const int4*>(subj + t0 + 4));
    const int4 ra = __ldg(reinterpret_cast<const int4*>(rel  + t0));
    const int4 rb = __ldg(reinterpret_cast<const int4*>(rel  + t0 + 4));
    const int4 oa = __ldg(reinterpret_cast<const int4*>(obj  + t0));
    const int4 ob = __ldg(reinterpret_cast<const int4*>(obj  + t0 + 4));

    const unsigned l0 = atomicAdd(&g_cursor[oa.x], 1u);
    const unsigned l1 = atomicAdd(&g_cursor[oa.y], 1u);
    const unsigned l2 = atomicAdd(&g_cursor[oa.z], 1u);
    const unsigned l3 = atomicAdd(&g_cursor[oa.w], 1u);
    const unsigned l4 = atomicAdd(&g_cursor[ob.x], 1u);
    const unsigned l5 = atomicAdd(&g_cursor[ob.y], 1u);
    const unsigned l6 = atomicAdd(&g_cursor[ob.z], 1u);
    const unsigned l7 = atomicAdd(&g_cursor[ob.w], 1u);

    g_sp[l0] = make_uint2(((unsigned)sa.x << 8) | (unsigned)ra.x, (unsigned)oa.x);
    g_sp[l1] = make_uint2(((unsigned)sa.y << 8) | (unsigned)ra.y, (unsigned)oa.y);
    g_sp[l2] = make_uint2(((unsigned)sa.z << 8) | (unsigned)ra.z, (unsigned)oa.z);
    g_sp[l3] = make_uint2(((unsigned)sa.w << 8) | (unsigned)ra.w, (unsigned)oa.w);
    g_sp[l4] = make_uint2(((unsigned)sb.x << 8) | (unsigned)rb.x, (unsigned)ob.x);
    g_sp[l5] = make_uint2(((unsigned)sb.y << 8) | (unsigned)rb.y, (unsigned)ob.y);
    g_sp[l6] = make_uint2(((unsigned)sb.z << 8) | (unsigned)rb.z, (unsigned)ob.z);
    g_sp[l7] = make_uint2(((unsigned)sb.w << 8) | (unsigned)rb.w, (unsigned)ob.w);
}

// ---------------------------------------------------------------------------
// One hop, strip form: thread = (strip of 8 sorted triples) x (4-batch chunk).
// Prefetch 8 x-gathers + 8 rt rows (MLP 16), fp32 accumulate, emit a vector
// red only at run boundaries (~2.4 per strip instead of 8).
// ---------------------------------------------------------------------------
__device__ __forceinline__ void red_v4(float* dst, float4 m) {
    asm volatile("red.global.add.v4.f32 [%0], {%1,%2,%3,%4};"
                 :: "l"(dst), "f"(m.x), "f"(m.y), "f"(m.z), "f"(m.w)
                 : "memory");
}

__global__ void __launch_bounds__(256, 3)
hop_strip(int hop, const int* __restrict__ n_hop) {
    if (hop >= *n_hop) return;
    const int tid = blockIdx.x * 256 + threadIdx.x;
    const int s   = tid >> 4;                 // strip index
    if (s >= N_T / STRIP) return;
    const int c   = tid & 15;                 // chunk: 4 batch elems (8B fp16)
    const int t0  = s * STRIP;

    const __half* __restrict__ xt = g_x16;
    const __half* __restrict__ rt = g_rt16[hop];

    // 8 (pack, obj) pairs; plain __ldg so g_sp stays L2-resident across hops.
    const uint4 a0 = __ldg(reinterpret_cast<const uint4*>(&g_sp[t0]));
    const uint4 a1 = __ldg(reinterpret_cast<const uint4*>(&g_sp[t0 + 2]));
    const uint4 a2 = __ldg(reinterpret_cast<const uint4*>(&g_sp[t0 + 4]));
    const uint4 a3 = __ldg(reinterpret_cast<const uint4*>(&g_sp[t0 + 6]));
    unsigned pk[STRIP] = {a0.x, a0.z, a1.x, a1.z, a2.x, a2.z, a3.x, a3.z};
    unsigned ob[STRIP] = {a0.y, a0.w, a1.y, a1.w, a2.y, a2.w, a3.y, a3.w};

    h4 xv[STRIP], rv[STRIP];
#pragma unroll
    for (int j = 0; j < STRIP; ++j)
        xv[j] = reinterpret_cast<const h4*>(xt + (size_t)(pk[j] >> 8) * BB)[c];
#pragma unroll
    for (int j = 0; j < STRIP; ++j)
        rv[j] = reinterpret_cast<const h4*>(rt + (pk[j] & 255u) * BB)[c];

    float4 acc = make_float4(0.f, 0.f, 0.f, 0.f);
#pragma unroll
    for (int j = 0; j < STRIP; ++j) {
        const float2 xl = __half22float2(xv[j].a), xh = __half22float2(xv[j].b);
        const float2 rl = __half22float2(rv[j].a), rh = __half22float2(rv[j].b);
        acc.x = fmaf(xl.x, rl.x, acc.x);
        acc.y = fmaf(xl.y, rl.y, acc.y);
        acc.z = fmaf(xh.x, rh.x, acc.z);
        acc.w = fmaf(xh.y, rh.y, acc.w);
        const bool emit = (j == STRIP - 1) || (ob[j] != ob[j + 1]);
        if (emit) {
            red_v4(g_y32 + (size_t)ob[j] * BB + c * 4, acc);
            acc = make_float4(0.f, 0.f, 0.f, 0.f);
        }
    }
}

// ---------------------------------------------------------------------------
// Between hops: x16 = fp16(y32); y32 = 0. Guarded on hop+1 < n_hop.
// y32 read is evict-first (.cs): its contents are dead after this pass.
// ---------------------------------------------------------------------------
__global__ void __launch_bounds__(256)
convert_zero(int hop, const int* __restrict__ n_hop) {
    if (hop + 1 >= *n_hop) return;
    const size_t i = (size_t)blockIdx.x * blockDim.x + threadIdx.x;
    float4* __restrict__ y4 = reinterpret_cast<float4*>(g_y32);
    float4 v;
    asm volatile("ld.global.cs.v4.f32 {%0,%1,%2,%3}, [%4];"
                 : "=f"(v.x), "=f"(v.y), "=f"(v.z), "=f"(v.w) : "l"(y4 + i));
    h4 o;
    o.a = __floats2half2_rn(v.x, v.y);
    o.b = __floats2half2_rn(v.z, v.w);
    reinterpret_cast<h4*>(g_x16)[i] = o;
    y4[i] = make_float4(0.f, 0.f, 0.f, 0.f);
}

// ---------------------------------------------------------------------------
// Final transpose g_y32 (N_E,64) -> out (B,N_E); if n_hop==0, out = x.
// ---------------------------------------------------------------------------
__global__ void transpose_out(float* __restrict__ out,
                              const float* __restrict__ x,
                              const int* __restrict__ n_hop) {
    __shared__ float tile[32][BB + 1];
    const int tid = threadIdx.x;

    if (*n_hop == 0) {   // identity: copy x -> out
        const size_t n = (size_t)BB * N_E;
        const size_t stride = (size_t)gridDim.x * blockDim.x;
        for (size_t i = (size_t)blockIdx.x * blockDim.x + tid; i < n; i += stride)
            out[i] = x[i];
        return;
    }

    const int e0 = blockIdx.x * 32;
    const int f4 = tid & 15;
    for (int er = tid >> 4; er < 32; er += 16) {
        const int e = e0 + er;
        float4 v = make_float4(0.f, 0.f, 0.f, 0.f);
        if (e < N_E)
            v = reinterpret_cast<const float4*>(&g_y32[(size_t)e * BB])[f4];
        tile[er][f4 * 4 + 0] = v.x;
        tile[er][f4 * 4 + 1] = v.y;
        tile[er][f4 * 4 + 2] = v.z;
        tile[er][f4 * 4 + 3] = v.w;
    }
    __syncthreads();

    const int lane = tid & 31;
    const int warp = tid >> 5;
    for (int b = warp; b < BB; b += 8) {
        const int e = e0 + lane;
        if (e < N_E) out[(size_t)b * N_E + e] = tile[lane][b];
    }
}

// ---------------------------------------------------------------------------
// Launch
// ---------------------------------------------------------------------------
extern "C" void kernel_launch(void* const* d_in, const int* in_sizes, int n_in,
                              void* d_out, int out_size) {
    const float* x    = (const float*)d_in[0];
    const float* q    = (const float*)d_in[1];
    const float* W1   = (const float*)d_in[2];
    const float* b1   = (const float*)d_in[3];
    const float* W2   = (const float*)d_in[4];
    const float* b2   = (const float*)d_in[5];
    const float* W3   = (const float*)d_in[6];
    const float* b3   = (const float*)d_in[7];
    const int*   subj = (const int*)d_in[8];
    const int*   rel  = (const int*)d_in[9];
    const int*   obj  = (const int*)d_in[10];
    const int*   nhop = (const int*)d_in[11];
    float*       out  = (float*)d_out;

    transpose_in<<<TB_TILES + CR_BLKS, 256>>>(x, q, W1, b1, W2, b2, W3, b3);

    csr_count<<<(N_T / 8 + 255) / 256, 256>>>(obj);
    csr_scan1<<<SCAN_NBLK, 512>>>();
    csr_scan23<<<(N_E + 255) / 256, 256>>>();
    csr_scatter<<<(N_T / 8 + 255) / 256, 256>>>(subj, rel, obj);

    const int hop_threads = (N_T / STRIP) * 16;       // 2M
    const int hop_blocks  = (hop_threads + 255) / 256;
    const int cv_blocks   = (N_E * BB / 4 + 255) / 256;

    for (int h = 0; h < 3; ++h) {
        hop_strip<<<hop_blocks, 256>>>(h, nhop);
        convert_zero<<<cv_blocks, 256>>>(h, nhop);    // no-op for last hop
    }

    transpose_out<<<TB_TILES, 256>>>(out, x, nhop);
}